// round 3
// baseline (speedup 1.0000x reference)
#include <cuda_runtime.h>
#include <cstdint>
#include <cstddef>

// Problem constants (fixed shapes for this problem instance)
#define NN   100000   // nodes
#define HH   96       // hidden
#define AA   32       // attn dim
#define EE   500000   // edges per type
#define PC   580      // packed GEMM output columns: 6*96 A/B blocks + 4 attn scalars
#define PCPAD 640     // padded col count for tiling

// ---------------- device scratch (allocation-free rule: __device__ globals) ----
__device__ float g_P[(size_t)NN * PC];          // 232 MB: A0|B0|A1|B1|A2|B2|el0|er0|el1|er1
__device__ float g_Wpack[PCPAD * HH];           // [col][k]
__device__ float g_CB[3 * HH];                  // c_t = ef_t @ Wm_t[192:] + bm_t
__device__ float g_num0[(size_t)NN * HH];
__device__ float g_num1[(size_t)NN * HH];
__device__ float g_sum2[(size_t)NN * HH];
__device__ float g_den0[NN];
__device__ float g_den1[NN];
__device__ float g_cnt2[NN];
__device__ float g_w0[EE];
__device__ float g_w1[EE];
__device__ float g_X[(size_t)NN * 384];         // [h | msg0 | msg1 | msg2]

// ---------------- helpers ------------------------------------------------------
__device__ __forceinline__ void red_add_v4(float* addr, float x, float y, float z, float w) {
    asm volatile("red.global.add.v4.f32 [%0], {%1, %2, %3, %4};"
                 :: "l"(addr), "f"(x), "f"(y), "f"(z), "f"(w) : "memory");
}

// ---------------- zero init ----------------------------------------------------
__global__ void zero_kernel() {
    size_t i = (size_t)blockIdx.x * blockDim.x + threadIdx.x;
    size_t stride = (size_t)gridDim.x * blockDim.x;
    size_t n4 = ((size_t)NN * HH) / 4;
    float4 z = make_float4(0.f, 0.f, 0.f, 0.f);
    for (size_t k = i; k < n4; k += stride) {
        reinterpret_cast<float4*>(g_num0)[k] = z;
        reinterpret_cast<float4*>(g_num1)[k] = z;
        reinterpret_cast<float4*>(g_sum2)[k] = z;
    }
    for (size_t k = i; k < NN; k += stride) {
        g_den0[k] = 0.f; g_den1[k] = 0.f; g_cnt2[k] = 0.f;
    }
}

// ---------------- weight packing ----------------------------------------------
// Wpack[j][k]: col j of P is sum_k h[:,k] * Wpack[j][k]
__global__ void pack_w_kernel(const float* __restrict__ Wm0, const float* __restrict__ Wm1,
                              const float* __restrict__ Wm2,
                              const float* __restrict__ Wn0, const float* __restrict__ Wa0,
                              const float* __restrict__ Wn1, const float* __restrict__ Wa1) {
    int gid = blockIdx.x * blockDim.x + threadIdx.x;
    if (gid >= PCPAD * HH) return;
    int j = gid / HH;     // output column
    int k = gid % HH;     // input feature
    float v = 0.f;
    if (j < 576) {
        int b = j / HH;           // 0..5  (A0,B0,A1,B1,A2,B2)
        int jj = j % HH;
        int t = b >> 1;
        int rowoff = (b & 1) * HH;
        const float* Wm = (t == 0) ? Wm0 : (t == 1) ? Wm1 : Wm2;
        v = Wm[(size_t)(rowoff + k) * HH + jj];   // Wm is [208][96] row-major
    } else if (j < PC) {
        int q = j - 576;          // 0:el0 1:er0 2:el1 3:er1
        const float* Wn = (q < 2) ? Wn0 : Wn1;
        const float* Wa = (q < 2) ? Wa0 : Wa1;
        int off = (q & 1) * AA;
        float s = 0.f;
        #pragma unroll
        for (int a = 0; a < AA; a++) s += Wn[(size_t)k * AA + a] * Wa[off + a];
        v = s;
    }
    g_Wpack[(size_t)j * HH + k] = v;
}

__global__ void pack_c_kernel(const float* __restrict__ Wm0, const float* __restrict__ bm0,
                              const float* __restrict__ ef0,
                              const float* __restrict__ Wm1, const float* __restrict__ bm1,
                              const float* __restrict__ ef1,
                              const float* __restrict__ Wm2, const float* __restrict__ bm2,
                              const float* __restrict__ ef2) {
    int gid = threadIdx.x;
    if (gid >= 3 * HH) return;
    int t = gid / HH, j = gid % HH;
    const float* Wm = (t == 0) ? Wm0 : (t == 1) ? Wm1 : Wm2;
    const float* bm = (t == 0) ? bm0 : (t == 1) ? bm1 : bm2;
    const float* ef = (t == 0) ? ef0 : (t == 1) ? ef1 : ef2;
    float s = bm[j];
    #pragma unroll
    for (int d = 0; d < 16; d++) s += ef[d] * Wm[(size_t)(192 + d) * HH + j];
    g_CB[gid] = s;
}

// ---------------- GEMM 1: P = h @ Wcat  (M=N, K=96, Ncols=580) ------------------
// BM=64, BN=64, BK=32, 256 threads, 4x4 micro-tile
__global__ void __launch_bounds__(256) gemm_p_kernel(const float* __restrict__ h, int Nn) {
    __shared__ float As[32][68];
    __shared__ float Bs[32][68];
    const int bm = blockIdx.y * 64;
    const int bn = blockIdx.x * 64;
    const int tid = threadIdx.x;
    const int tr = (tid >> 4) << 2;
    const int tc = (tid & 15) << 2;
    float acc[4][4] = {};
    for (int k0 = 0; k0 < HH; k0 += 32) {
        #pragma unroll
        for (int it = 0; it < 2; it++) {
            int q = tid + it * 256;       // 0..511
            int m = q >> 3;               // 0..63
            int kq = (q & 7) << 2;        // 0,4,...,28
            float4 v = make_float4(0.f, 0.f, 0.f, 0.f);
            int grow = bm + m;
            if (grow < Nn) v = *reinterpret_cast<const float4*>(&h[(size_t)grow * HH + k0 + kq]);
            As[kq + 0][m] = v.x; As[kq + 1][m] = v.y; As[kq + 2][m] = v.z; As[kq + 3][m] = v.w;
            float4 w = *reinterpret_cast<const float4*>(&g_Wpack[(size_t)(bn + m) * HH + k0 + kq]);
            Bs[kq + 0][m] = w.x; Bs[kq + 1][m] = w.y; Bs[kq + 2][m] = w.z; Bs[kq + 3][m] = w.w;
        }
        __syncthreads();
        #pragma unroll
        for (int kk = 0; kk < 32; kk++) {
            float4 a = *reinterpret_cast<const float4*>(&As[kk][tr]);
            float4 b = *reinterpret_cast<const float4*>(&Bs[kk][tc]);
            acc[0][0] += a.x * b.x; acc[0][1] += a.x * b.y; acc[0][2] += a.x * b.z; acc[0][3] += a.x * b.w;
            acc[1][0] += a.y * b.x; acc[1][1] += a.y * b.y; acc[1][2] += a.y * b.z; acc[1][3] += a.y * b.w;
            acc[2][0] += a.z * b.x; acc[2][1] += a.z * b.y; acc[2][2] += a.z * b.z; acc[2][3] += a.z * b.w;
            acc[3][0] += a.w * b.x; acc[3][1] += a.w * b.y; acc[3][2] += a.w * b.z; acc[3][3] += a.w * b.w;
        }
        __syncthreads();
    }
    int colbase = bn + tc;
    if (colbase < PC) {   // PC multiple of 4 -> whole float4 valid or none
        #pragma unroll
        for (int i = 0; i < 4; i++) {
            int row = bm + tr + i;
            if (row < Nn) {
                float4 v = make_float4(acc[i][0], acc[i][1], acc[i][2], acc[i][3]);
                *reinterpret_cast<float4*>(&g_P[(size_t)row * PC + colbase]) = v;
            }
        }
    }
}

// ---------------- edge weight kernels ------------------------------------------
__global__ void edge_w_kernel(const int* __restrict__ src, const int* __restrict__ dst,
                              int elo, int ero, int which, int E) {
    int e = blockIdx.x * blockDim.x + threadIdx.x;
    if (e >= E) return;
    int s = src[e], d = dst[e];
    float sc = __ldg(&g_P[(size_t)s * PC + elo]) + __ldg(&g_P[(size_t)d * PC + ero]);
    sc = (sc > 0.f) ? sc : 0.01f * sc;
    float w = expf(sc);
    float* wbuf = (which == 0) ? g_w0 : g_w1;
    float* den  = (which == 0) ? g_den0 : g_den1;
    wbuf[e] = w;
    atomicAdd(&den[d], w);
}

__global__ void count_kernel(const int* __restrict__ dst, int E) {
    int e = blockIdx.x * blockDim.x + threadIdx.x;
    if (e >= E) return;
    atomicAdd(&g_cnt2[dst[e]], 1.0f);
}

// ---------------- scatter kernels (24 threads / edge, vector atomics) ----------
__global__ void scatter_w_kernel(const int* __restrict__ src, const int* __restrict__ dst,
                                 int aoff, int which, int E) {
    int gid = blockIdx.x * blockDim.x + threadIdx.x;
    if (gid >= E * 24) return;
    int e = gid / 24;
    int c = gid % 24;
    int s = src[e], d = dst[e];
    const float* wbuf = (which == 0) ? g_w0 : g_w1;
    float* num = (which == 0) ? g_num0 : g_num1;
    float w = __ldg(&wbuf[e]);
    float4 a = *reinterpret_cast<const float4*>(&g_P[(size_t)s * PC + aoff + c * 4]);
    red_add_v4(&num[(size_t)d * HH + c * 4], a.x * w, a.y * w, a.z * w, a.w * w);
}

__global__ void scatter_mean_kernel(const int* __restrict__ src, const int* __restrict__ dst,
                                    int aoff, int E) {
    int gid = blockIdx.x * blockDim.x + threadIdx.x;
    if (gid >= E * 24) return;
    int e = gid / 24;
    int c = gid % 24;
    int s = src[e], d = dst[e];
    float4 a = *reinterpret_cast<const float4*>(&g_P[(size_t)s * PC + aoff + c * 4]);
    red_add_v4(&g_sum2[(size_t)d * HH + c * 4], a.x, a.y, a.z, a.w);
}

// ---------------- finalize: X = [h | msg0 | msg1 | msg2] -----------------------
__global__ void finalize_kernel(const float* __restrict__ h, int Nn) {
    int gid = blockIdx.x * blockDim.x + threadIdx.x;
    int n = gid / 24;
    int c = gid % 24;
    if (n >= Nn) return;
    int c4 = c * 4;
    size_t pr = (size_t)n * PC;
    size_t nr = (size_t)n * HH;
    float4 hv = *reinterpret_cast<const float4*>(&h[nr + c4]);
    float4 b0 = *reinterpret_cast<const float4*>(&g_P[pr + 96 + c4]);
    float4 b1 = *reinterpret_cast<const float4*>(&g_P[pr + 288 + c4]);
    float4 b2 = *reinterpret_cast<const float4*>(&g_P[pr + 480 + c4]);
    float d0 = g_den0[n], d1 = g_den1[n], ct = g_cnt2[n];
    float4 n0 = *reinterpret_cast<const float4*>(&g_num0[nr + c4]);
    float4 n1 = *reinterpret_cast<const float4*>(&g_num1[nr + c4]);
    float4 s2 = *reinterpret_cast<const float4*>(&g_sum2[nr + c4]);
    float4 cb0 = *reinterpret_cast<const float4*>(&g_CB[0 * HH + c4]);
    float4 cb1 = *reinterpret_cast<const float4*>(&g_CB[1 * HH + c4]);
    float4 cb2 = *reinterpret_cast<const float4*>(&g_CB[2 * HH + c4]);

    float4 m0 = make_float4(0.f, 0.f, 0.f, 0.f);
    float4 m1 = make_float4(0.f, 0.f, 0.f, 0.f);
    float4 m2 = make_float4(0.f, 0.f, 0.f, 0.f);
    if (d0 > 0.f) {
        float r = 1.f / d0;
        m0 = make_float4(n0.x * r + b0.x + cb0.x, n0.y * r + b0.y + cb0.y,
                         n0.z * r + b0.z + cb0.z, n0.w * r + b0.w + cb0.w);
    }
    if (d1 > 0.f) {
        float r = 1.f / d1;
        m1 = make_float4(n1.x * r + b1.x + cb1.x, n1.y * r + b1.y + cb1.y,
                         n1.z * r + b1.z + cb1.z, n1.w * r + b1.w + cb1.w);
    }
    if (ct > 0.f) {
        float r = 1.f / ct;
        m2 = make_float4(s2.x * r + b2.x + cb2.x, s2.y * r + b2.y + cb2.y,
                         s2.z * r + b2.z + cb2.z, s2.w * r + b2.w + cb2.w);
    }
    size_t xr = (size_t)n * 384;
    *reinterpret_cast<float4*>(&g_X[xr + 0   + c4]) = hv;
    *reinterpret_cast<float4*>(&g_X[xr + 96  + c4]) = m0;
    *reinterpret_cast<float4*>(&g_X[xr + 192 + c4]) = m1;
    *reinterpret_cast<float4*>(&g_X[xr + 288 + c4]) = m2;
}

// ---------------- GEMM 2: out = relu(X @ Wu + bu)  (M=N, K=384, Ncols=96) ------
// BM=64, BN=96, BK=32, 256 threads, 4x6 micro-tile
__global__ void __launch_bounds__(256) gemm_out_kernel(const float* __restrict__ Wu,
                                                       const float* __restrict__ bu,
                                                       float* __restrict__ out, int Nn) {
    __shared__ float As[32][68];
    __shared__ float Bs[32][100];
    const int bm = blockIdx.x * 64;
    const int tid = threadIdx.x;
    const int tr = (tid >> 4) << 2;       // row in tile
    const int tc = (tid & 15) * 6;        // col in [0,96)
    float acc[4][6] = {};
    for (int k0 = 0; k0 < 384; k0 += 32) {
        #pragma unroll
        for (int it = 0; it < 2; it++) {
            int q = tid + it * 256;       // 0..511
            int m = q >> 3;
            int kq = (q & 7) << 2;
            float4 v = make_float4(0.f, 0.f, 0.f, 0.f);
            int grow = bm + m;
            if (grow < Nn) v = *reinterpret_cast<const float4*>(&g_X[(size_t)grow * 384 + k0 + kq]);
            As[kq + 0][m] = v.x; As[kq + 1][m] = v.y; As[kq + 2][m] = v.z; As[kq + 3][m] = v.w;
        }
        #pragma unroll
        for (int it = 0; it < 3; it++) {
            int q = tid + it * 256;       // 0..767 ; 24 float4 per k-row
            int k = q / 24;
            int cq = (q % 24) * 4;
            float4 w = *reinterpret_cast<const float4*>(&Wu[(size_t)(k0 + k) * HH + cq]);
            Bs[k][cq + 0] = w.x; Bs[k][cq + 1] = w.y; Bs[k][cq + 2] = w.z; Bs[k][cq + 3] = w.w;
        }
        __syncthreads();
        #pragma unroll
        for (int kk = 0; kk < 32; kk++) {
            float4 a = *reinterpret_cast<const float4*>(&As[kk][tr]);
            float2 b01 = *reinterpret_cast<const float2*>(&Bs[kk][tc]);
            float2 b23 = *reinterpret_cast<const float2*>(&Bs[kk][tc + 2]);
            float2 b45 = *reinterpret_cast<const float2*>(&Bs[kk][tc + 4]);
            float bb[6] = {b01.x, b01.y, b23.x, b23.y, b45.x, b45.y};
            float aa[4] = {a.x, a.y, a.z, a.w};
            #pragma unroll
            for (int i = 0; i < 4; i++)
                #pragma unroll
                for (int j = 0; j < 6; j++)
                    acc[i][j] += aa[i] * bb[j];
        }
        __syncthreads();
    }
    #pragma unroll
    for (int i = 0; i < 4; i++) {
        int row = bm + tr + i;
        if (row < Nn) {
            #pragma unroll
            for (int j = 0; j < 6; j++) {
                float v = acc[i][j] + __ldg(&bu[tc + j]);
                out[(size_t)row * HH + tc + j] = fmaxf(v, 0.f);
            }
        }
    }
}

// ---------------- launch -------------------------------------------------------
extern "C" void kernel_launch(void* const* d_in, const int* in_sizes, int n_in,
                              void* d_out, int out_size) {
    const float* h    = (const float*)d_in[0];
    const int*   src0 = (const int*)d_in[1];
    const int*   dst0 = (const int*)d_in[2];
    const int*   src1 = (const int*)d_in[3];
    const int*   dst1 = (const int*)d_in[4];
    const int*   src2 = (const int*)d_in[5];
    const int*   dst2 = (const int*)d_in[6];
    const float* Wm0  = (const float*)d_in[7];
    const float* bm0  = (const float*)d_in[8];
    const float* ef0  = (const float*)d_in[9];
    const float* Wm1  = (const float*)d_in[10];
    const float* bm1  = (const float*)d_in[11];
    const float* ef1  = (const float*)d_in[12];
    const float* Wm2  = (const float*)d_in[13];
    const float* bm2  = (const float*)d_in[14];
    const float* ef2  = (const float*)d_in[15];
    const float* Wn0  = (const float*)d_in[16];
    const float* Wa0  = (const float*)d_in[17];
    const float* Wn1  = (const float*)d_in[18];
    const float* Wa1  = (const float*)d_in[19];
    const float* Wu   = (const float*)d_in[20];
    const float* bu   = (const float*)d_in[21];
    float* out = (float*)d_out;

    int Nn = in_sizes[0] / HH;
    int E0 = in_sizes[1];
    int E1 = in_sizes[3];
    int E2 = in_sizes[5];

    zero_kernel<<<2048, 256>>>();
    pack_w_kernel<<<(PCPAD * HH + 255) / 256, 256>>>(Wm0, Wm1, Wm2, Wn0, Wa0, Wn1, Wa1);
    pack_c_kernel<<<1, 3 * HH>>>(Wm0, bm0, ef0, Wm1, bm1, ef1, Wm2, bm2, ef2);

    dim3 g1((PCPAD + 63) / 64, (Nn + 63) / 64);
    gemm_p_kernel<<<g1, 256>>>(h, Nn);

    edge_w_kernel<<<(E0 + 255) / 256, 256>>>(src0, dst0, 576, 577, 0, E0);
    edge_w_kernel<<<(E1 + 255) / 256, 256>>>(src1, dst1, 578, 579, 1, E1);
    count_kernel<<<(E2 + 255) / 256, 256>>>(dst2, E2);

    scatter_w_kernel<<<(E0 * 24 + 255) / 256, 256>>>(src0, dst0, 0,   0, E0);
    scatter_w_kernel<<<(E1 * 24 + 255) / 256, 256>>>(src1, dst1, 192, 1, E1);
    scatter_mean_kernel<<<(E2 * 24 + 255) / 256, 256>>>(src2, dst2, 384, E2);

    finalize_kernel<<<(Nn * 24 + 255) / 256, 256>>>(h, Nn);

    gemm_out_kernel<<<(Nn + 63) / 64, 256>>>(Wu, bu, out, Nn);
}

// round 5
// speedup vs baseline: 1.1647x; 1.1647x over previous
#include <cuda_runtime.h>
#include <cstdint>
#include <cstddef>

// Problem constants (fixed shapes for this problem instance)
#define NN   100000   // nodes
#define HH   96       // hidden
#define AA   32       // attn dim
#define EE   500000   // edges per type
#define PC   580      // packed GEMM output columns: 6*96 A/B blocks + 4 attn scalars
#define PCPAD 640     // padded col count for tiling

// ---------------- device scratch (allocation-free rule: __device__ globals) ----
__device__ float g_P[(size_t)NN * PC];          // 232 MB: A0|B0|A1|B1|A2|B2|el0|er0|el1|er1
__device__ float g_Wpack[PCPAD * HH];           // [col][k]
__device__ float g_CB[3 * HH];                  // c_t = ef_t @ Wm_t[192:] + bm_t
__device__ float g_num0[(size_t)NN * HH];
__device__ float g_num1[(size_t)NN * HH];
__device__ float g_sum2[(size_t)NN * HH];
__device__ float g_den0[NN];
__device__ float g_den1[NN];
__device__ float g_cnt2[NN];
__device__ float g_w0[EE];
__device__ float g_w1[EE];
__device__ float g_X[(size_t)NN * 384];         // [h | msg0 | msg1 | msg2]

// ---------------- helpers ------------------------------------------------------
__device__ __forceinline__ void red_add_v4(float* addr, float x, float y, float z, float w) {
    asm volatile("red.global.add.v4.f32 [%0], {%1, %2, %3, %4};"
                 :: "l"(addr), "f"(x), "f"(y), "f"(z), "f"(w) : "memory");
}

// packed f32x2 ops (Blackwell dual-rate fp32; ptxas never emits FFMA2 from C++)
__device__ __forceinline__ unsigned long long pk2(float lo, float hi) {
    unsigned long long r;
    asm("mov.b64 %0, {%1, %2};" : "=l"(r) : "f"(lo), "f"(hi));
    return r;
}
__device__ __forceinline__ void upk2(unsigned long long v, float& lo, float& hi) {
    asm("mov.b64 {%0, %1}, %2;" : "=f"(lo), "=f"(hi) : "l"(v));
}
__device__ __forceinline__ void fma2(unsigned long long& d, unsigned long long a, unsigned long long b) {
    asm("fma.rn.f32x2 %0, %1, %2, %3;" : "=l"(d) : "l"(a), "l"(b), "l"(d));
}

// ---------------- zero init ----------------------------------------------------
__global__ void zero_kernel() {
    size_t i = (size_t)blockIdx.x * blockDim.x + threadIdx.x;
    size_t stride = (size_t)gridDim.x * blockDim.x;
    size_t n4 = ((size_t)NN * HH) / 4;
    float4 z = make_float4(0.f, 0.f, 0.f, 0.f);
    for (size_t k = i; k < n4; k += stride) {
        reinterpret_cast<float4*>(g_num0)[k] = z;
        reinterpret_cast<float4*>(g_num1)[k] = z;
        reinterpret_cast<float4*>(g_sum2)[k] = z;
    }
    for (size_t k = i; k < NN; k += stride) {
        g_den0[k] = 0.f; g_den1[k] = 0.f; g_cnt2[k] = 0.f;
    }
}

// ---------------- weight packing ----------------------------------------------
__global__ void pack_w_kernel(const float* __restrict__ Wm0, const float* __restrict__ Wm1,
                              const float* __restrict__ Wm2,
                              const float* __restrict__ Wn0, const float* __restrict__ Wa0,
                              const float* __restrict__ Wn1, const float* __restrict__ Wa1) {
    int gid = blockIdx.x * blockDim.x + threadIdx.x;
    if (gid >= PCPAD * HH) return;
    int j = gid / HH;     // output column
    int k = gid % HH;     // input feature
    float v = 0.f;
    if (j < 576) {
        int b = j / HH;           // 0..5  (A0,B0,A1,B1,A2,B2)
        int jj = j % HH;
        int t = b >> 1;
        int rowoff = (b & 1) * HH;
        const float* Wm = (t == 0) ? Wm0 : (t == 1) ? Wm1 : Wm2;
        v = Wm[(size_t)(rowoff + k) * HH + jj];
    } else if (j < PC) {
        int q = j - 576;          // 0:el0 1:er0 2:el1 3:er1
        const float* Wn = (q < 2) ? Wn0 : Wn1;
        const float* Wa = (q < 2) ? Wa0 : Wa1;
        int off = (q & 1) * AA;
        float s = 0.f;
        #pragma unroll
        for (int a = 0; a < AA; a++) s += Wn[(size_t)k * AA + a] * Wa[off + a];
        v = s;
    }
    g_Wpack[(size_t)j * HH + k] = v;
}

__global__ void pack_c_kernel(const float* __restrict__ Wm0, const float* __restrict__ bm0,
                              const float* __restrict__ ef0,
                              const float* __restrict__ Wm1, const float* __restrict__ bm1,
                              const float* __restrict__ ef1,
                              const float* __restrict__ Wm2, const float* __restrict__ bm2,
                              const float* __restrict__ ef2) {
    int gid = threadIdx.x;
    if (gid >= 3 * HH) return;
    int t = gid / HH, j = gid % HH;
    const float* Wm = (t == 0) ? Wm0 : (t == 1) ? Wm1 : Wm2;
    const float* bm = (t == 0) ? bm0 : (t == 1) ? bm1 : bm2;
    const float* ef = (t == 0) ? ef0 : (t == 1) ? ef1 : ef2;
    float s = bm[j];
    #pragma unroll
    for (int d = 0; d < 16; d++) s += ef[d] * Wm[(size_t)(192 + d) * HH + j];
    g_CB[gid] = s;
}

// ---------------- GEMM 1: P = h @ Wcat  (M=N, K=96, Ncols=580) ------------------
// BM=128, BN=128, BK=16, 256 threads, 8x8 micro-tile, packed f32x2 FMA
__global__ void __launch_bounds__(256) gemm_p_kernel(const float* __restrict__ h, int Nn) {
    __shared__ float As[16][132];
    __shared__ float Bs[16][132];
    const int bm = blockIdx.y * 128;
    const int bn = blockIdx.x * 128;
    const int tid = threadIdx.x;
    const int tr = (tid >> 4) << 2;   // 0..60
    const int tc = (tid & 15) << 2;   // 0..60
    unsigned long long acc[8][4];
    #pragma unroll
    for (int i = 0; i < 8; i++)
        #pragma unroll
        for (int j = 0; j < 4; j++) acc[i][j] = 0ull;

    for (int k0 = 0; k0 < HH; k0 += 16) {
        #pragma unroll
        for (int it = 0; it < 2; it++) {
            int q = tid + it * 256;         // 0..511
            int row = q >> 2;               // 0..127
            int kq = (q & 3) << 2;          // 0,4,8,12
            int grow = bm + row;
            float4 v = make_float4(0.f, 0.f, 0.f, 0.f);
            if (grow < Nn) v = *reinterpret_cast<const float4*>(&h[(size_t)grow * HH + k0 + kq]);
            As[kq + 0][row] = v.x; As[kq + 1][row] = v.y; As[kq + 2][row] = v.z; As[kq + 3][row] = v.w;
            float4 w = *reinterpret_cast<const float4*>(&g_Wpack[(size_t)(bn + row) * HH + k0 + kq]);
            Bs[kq + 0][row] = w.x; Bs[kq + 1][row] = w.y; Bs[kq + 2][row] = w.z; Bs[kq + 3][row] = w.w;
        }
        __syncthreads();
        #pragma unroll
        for (int kk = 0; kk < 16; kk++) {
            float4 a0 = *reinterpret_cast<const float4*>(&As[kk][tr]);
            float4 a1 = *reinterpret_cast<const float4*>(&As[kk][tr + 64]);
            float4 b0 = *reinterpret_cast<const float4*>(&Bs[kk][tc]);
            float4 b1 = *reinterpret_cast<const float4*>(&Bs[kk][tc + 64]);
            unsigned long long bb[4] = {pk2(b0.x, b0.y), pk2(b0.z, b0.w),
                                        pk2(b1.x, b1.y), pk2(b1.z, b1.w)};
            float aa[8] = {a0.x, a0.y, a0.z, a0.w, a1.x, a1.y, a1.z, a1.w};
            #pragma unroll
            for (int i = 0; i < 8; i++) {
                unsigned long long ar = pk2(aa[i], aa[i]);
                #pragma unroll
                for (int j = 0; j < 4; j++) fma2(acc[i][j], ar, bb[j]);
            }
        }
        __syncthreads();
    }

    #pragma unroll
    for (int i = 0; i < 8; i++) {
        int row = bm + ((i < 4) ? (tr + i) : (tr + 64 + i - 4));
        if (row >= Nn) continue;
        #pragma unroll
        for (int half = 0; half < 2; half++) {
            int colbase = bn + tc + half * 64;
            if (colbase < PC) {   // PC multiple of 4
                float4 v;
                upk2(acc[i][half * 2 + 0], v.x, v.y);
                upk2(acc[i][half * 2 + 1], v.z, v.w);
                *reinterpret_cast<float4*>(&g_P[(size_t)row * PC + colbase]) = v;
            }
        }
    }
}

// ---------------- edge weight kernels ------------------------------------------
__global__ void edge_w_kernel(const int* __restrict__ src, const int* __restrict__ dst,
                              int elo, int ero, int which, int E) {
    int e = blockIdx.x * blockDim.x + threadIdx.x;
    if (e >= E) return;
    int s = src[e], d = dst[e];
    float sc = __ldg(&g_P[(size_t)s * PC + elo]) + __ldg(&g_P[(size_t)d * PC + ero]);
    sc = (sc > 0.f) ? sc : 0.01f * sc;
    float w = expf(sc);
    float* wbuf = (which == 0) ? g_w0 : g_w1;
    float* den  = (which == 0) ? g_den0 : g_den1;
    wbuf[e] = w;
    atomicAdd(&den[d], w);
}

__global__ void count_kernel(const int* __restrict__ dst, int E) {
    int e = blockIdx.x * blockDim.x + threadIdx.x;
    if (e >= E) return;
    atomicAdd(&g_cnt2[dst[e]], 1.0f);
}

// ---------------- scatter kernels (24 threads / edge, vector atomics) ----------
__global__ void scatter_w_kernel(const int* __restrict__ src, const int* __restrict__ dst,
                                 int aoff, int which, int E) {
    int gid = blockIdx.x * blockDim.x + threadIdx.x;
    if (gid >= E * 24) return;
    int e = gid / 24;
    int c = gid % 24;
    int s = src[e], d = dst[e];
    const float* wbuf = (which == 0) ? g_w0 : g_w1;
    float* num = (which == 0) ? g_num0 : g_num1;
    float w = __ldg(&wbuf[e]);
    float4 a = *reinterpret_cast<const float4*>(&g_P[(size_t)s * PC + aoff + c * 4]);
    red_add_v4(&num[(size_t)d * HH + c * 4], a.x * w, a.y * w, a.z * w, a.w * w);
}

__global__ void scatter_mean_kernel(const int* __restrict__ src, const int* __restrict__ dst,
                                    int aoff, int E) {
    int gid = blockIdx.x * blockDim.x + threadIdx.x;
    if (gid >= E * 24) return;
    int e = gid / 24;
    int c = gid % 24;
    int s = src[e], d = dst[e];
    float4 a = *reinterpret_cast<const float4*>(&g_P[(size_t)s * PC + aoff + c * 4]);
    red_add_v4(&g_sum2[(size_t)d * HH + c * 4], a.x, a.y, a.z, a.w);
}

// ---------------- finalize: X = [h | msg0 | msg1 | msg2] -----------------------
__global__ void finalize_kernel(const float* __restrict__ h, int Nn) {
    int gid = blockIdx.x * blockDim.x + threadIdx.x;
    int n = gid / 24;
    int c = gid % 24;
    if (n >= Nn) return;
    int c4 = c * 4;
    size_t pr = (size_t)n * PC;
    size_t nr = (size_t)n * HH;
    float4 hv = *reinterpret_cast<const float4*>(&h[nr + c4]);
    float4 b0 = *reinterpret_cast<const float4*>(&g_P[pr + 96 + c4]);
    float4 b1 = *reinterpret_cast<const float4*>(&g_P[pr + 288 + c4]);
    float4 b2 = *reinterpret_cast<const float4*>(&g_P[pr + 480 + c4]);
    float d0 = g_den0[n], d1 = g_den1[n], ct = g_cnt2[n];
    float4 n0 = *reinterpret_cast<const float4*>(&g_num0[nr + c4]);
    float4 n1 = *reinterpret_cast<const float4*>(&g_num1[nr + c4]);
    float4 s2 = *reinterpret_cast<const float4*>(&g_sum2[nr + c4]);
    float4 cb0 = *reinterpret_cast<const float4*>(&g_CB[0 * HH + c4]);
    float4 cb1 = *reinterpret_cast<const float4*>(&g_CB[1 * HH + c4]);
    float4 cb2 = *reinterpret_cast<const float4*>(&g_CB[2 * HH + c4]);

    float4 m0 = make_float4(0.f, 0.f, 0.f, 0.f);
    float4 m1 = make_float4(0.f, 0.f, 0.f, 0.f);
    float4 m2 = make_float4(0.f, 0.f, 0.f, 0.f);
    if (d0 > 0.f) {
        float r = 1.f / d0;
        m0 = make_float4(n0.x * r + b0.x + cb0.x, n0.y * r + b0.y + cb0.y,
                         n0.z * r + b0.z + cb0.z, n0.w * r + b0.w + cb0.w);
    }
    if (d1 > 0.f) {
        float r = 1.f / d1;
        m1 = make_float4(n1.x * r + b1.x + cb1.x, n1.y * r + b1.y + cb1.y,
                         n1.z * r + b1.z + cb1.z, n1.w * r + b1.w + cb1.w);
    }
    if (ct > 0.f) {
        float r = 1.f / ct;
        m2 = make_float4(s2.x * r + b2.x + cb2.x, s2.y * r + b2.y + cb2.y,
                         s2.z * r + b2.z + cb2.z, s2.w * r + b2.w + cb2.w);
    }
    size_t xr = (size_t)n * 384;
    *reinterpret_cast<float4*>(&g_X[xr + 0   + c4]) = hv;
    *reinterpret_cast<float4*>(&g_X[xr + 96  + c4]) = m0;
    *reinterpret_cast<float4*>(&g_X[xr + 192 + c4]) = m1;
    *reinterpret_cast<float4*>(&g_X[xr + 288 + c4]) = m2;
}

// ---------------- GEMM 2: out = relu(X @ Wu + bu)  (M=N, K=384, Ncols=96) ------
// BM=128, BN=96, BK=16, 256 threads, 8x6 micro-tile, packed f32x2 FMA
__global__ void __launch_bounds__(256) gemm_out_kernel(const float* __restrict__ Wu,
                                                       const float* __restrict__ bu,
                                                       float* __restrict__ out, int Nn) {
    __shared__ float As[16][132];
    __shared__ float Bs[16][100];
    const int bm = blockIdx.x * 128;
    const int tid = threadIdx.x;
    const int tr = (tid >> 4) << 2;   // 0..60
    const int tc = (tid & 15) * 6;    // 0..90
    unsigned long long acc[8][3];
    #pragma unroll
    for (int i = 0; i < 8; i++)
        #pragma unroll
        for (int j = 0; j < 3; j++) acc[i][j] = 0ull;

    for (int k0 = 0; k0 < 384; k0 += 16) {
        #pragma unroll
        for (int it = 0; it < 2; it++) {
            int q = tid + it * 256;         // 0..511
            int row = q >> 2;               // 0..127
            int kq = (q & 3) << 2;
            int grow = bm + row;
            float4 v = make_float4(0.f, 0.f, 0.f, 0.f);
            if (grow < Nn) v = *reinterpret_cast<const float4*>(&g_X[(size_t)grow * 384 + k0 + kq]);
            As[kq + 0][row] = v.x; As[kq + 1][row] = v.y; As[kq + 2][row] = v.z; As[kq + 3][row] = v.w;
        }
        #pragma unroll
        for (int it = 0; it < 2; it++) {
            int q = tid + it * 256;         // need 384 float4 (16k x 24 f4)
            if (q < 384) {
                int k = q / 24;
                int cq = (q % 24) * 4;
                float4 w = *reinterpret_cast<const float4*>(&Wu[(size_t)(k0 + k) * HH + cq]);
                Bs[k][cq + 0] = w.x; Bs[k][cq + 1] = w.y; Bs[k][cq + 2] = w.z; Bs[k][cq + 3] = w.w;
            }
        }
        __syncthreads();
        #pragma unroll
        for (int kk = 0; kk < 16; kk++) {
            float4 a0 = *reinterpret_cast<const float4*>(&As[kk][tr]);
            float4 a1 = *reinterpret_cast<const float4*>(&As[kk][tr + 64]);
            float2 b0 = *reinterpret_cast<const float2*>(&Bs[kk][tc]);
            float2 b1 = *reinterpret_cast<const float2*>(&Bs[kk][tc + 2]);
            float2 b2 = *reinterpret_cast<const float2*>(&Bs[kk][tc + 4]);
            unsigned long long bb[3] = {pk2(b0.x, b0.y), pk2(b1.x, b1.y), pk2(b2.x, b2.y)};
            float aa[8] = {a0.x, a0.y, a0.z, a0.w, a1.x, a1.y, a1.z, a1.w};
            #pragma unroll
            for (int i = 0; i < 8; i++) {
                unsigned long long ar = pk2(aa[i], aa[i]);
                #pragma unroll
                for (int j = 0; j < 3; j++) fma2(acc[i][j], ar, bb[j]);
            }
        }
        __syncthreads();
    }

    float bias[6];
    #pragma unroll
    for (int j = 0; j < 6; j++) bias[j] = __ldg(&bu[tc + j]);

    #pragma unroll
    for (int i = 0; i < 8; i++) {
        int row = bm + ((i < 4) ? (tr + i) : (tr + 64 + i - 4));
        if (row >= Nn) continue;
        float v[6];
        upk2(acc[i][0], v[0], v[1]);
        upk2(acc[i][1], v[2], v[3]);
        upk2(acc[i][2], v[4], v[5]);
        #pragma unroll
        for (int j = 0; j < 6; j++)
            out[(size_t)row * HH + tc + j] = fmaxf(v[j] + bias[j], 0.f);
    }
}

// ---------------- launch -------------------------------------------------------
extern "C" void kernel_launch(void* const* d_in, const int* in_sizes, int n_in,
                              void* d_out, int out_size) {
    const float* h    = (const float*)d_in[0];
    const int*   src0 = (const int*)d_in[1];
    const int*   dst0 = (const int*)d_in[2];
    const int*   src1 = (const int*)d_in[3];
    const int*   dst1 = (const int*)d_in[4];
    const int*   src2 = (const int*)d_in[5];
    const int*   dst2 = (const int*)d_in[6];
    const float* Wm0  = (const float*)d_in[7];
    const float* bm0  = (const float*)d_in[8];
    const float* ef0  = (const float*)d_in[9];
    const float* Wm1  = (const float*)d_in[10];
    const float* bm1  = (const float*)d_in[11];
    const float* ef1  = (const float*)d_in[12];
    const float* Wm2  = (const float*)d_in[13];
    const float* bm2  = (const float*)d_in[14];
    const float* ef2  = (const float*)d_in[15];
    const float* Wn0  = (const float*)d_in[16];
    const float* Wa0  = (const float*)d_in[17];
    const float* Wn1  = (const float*)d_in[18];
    const float* Wa1  = (const float*)d_in[19];
    const float* Wu   = (const float*)d_in[20];
    const float* bu   = (const float*)d_in[21];
    float* out = (float*)d_out;

    int Nn = in_sizes[0] / HH;
    int E0 = in_sizes[1];
    int E1 = in_sizes[3];
    int E2 = in_sizes[5];

    zero_kernel<<<2048, 256>>>();
    pack_w_kernel<<<(PCPAD * HH + 255) / 256, 256>>>(Wm0, Wm1, Wm2, Wn0, Wa0, Wn1, Wa1);
    pack_c_kernel<<<1, 3 * HH>>>(Wm0, bm0, ef0, Wm1, bm1, ef1, Wm2, bm2, ef2);

    dim3 g1(PCPAD / 128, (Nn + 127) / 128);
    gemm_p_kernel<<<g1, 256>>>(h, Nn);

    edge_w_kernel<<<(E0 + 255) / 256, 256>>>(src0, dst0, 576, 577, 0, E0);
    edge_w_kernel<<<(E1 + 255) / 256, 256>>>(src1, dst1, 578, 579, 1, E1);
    count_kernel<<<(E2 + 255) / 256, 256>>>(dst2, E2);

    scatter_w_kernel<<<(E0 * 24 + 255) / 256, 256>>>(src0, dst0, 0,   0, E0);
    scatter_w_kernel<<<(E1 * 24 + 255) / 256, 256>>>(src1, dst1, 192, 1, E1);
    scatter_mean_kernel<<<(E2 * 24 + 255) / 256, 256>>>(src2, dst2, 384, E2);

    finalize_kernel<<<(Nn * 24 + 255) / 256, 256>>>(h, Nn);

    gemm_out_kernel<<<(Nn + 127) / 128, 256>>>(Wu, bu, out, Nn);
}

// round 9
// speedup vs baseline: 1.2805x; 1.0995x over previous
#include <cuda_runtime.h>
#include <cstdint>
#include <cstddef>

#define NN   100000   // nodes (max)
#define HH   96       // hidden
#define AA   32       // attn dim
#define EE   500000   // edges per type (max)
#define PC   580      // packed GEMM output columns
#define PCPAD 640     // padded col count for tiling

// ---------------- device scratch ----------------------------------------------
__device__ float g_P[(size_t)NN * PC];          // A0|B0|A1|B1|A2|B2|el0|er0|el1|er1
__device__ float g_WpackT[HH * PCPAD];          // k-major: [k][j]
__device__ float g_CB[3 * HH];
__device__ float g_w0[EE];
__device__ float g_w1[EE];
__device__ float g_X[(size_t)NN * 384];         // [h | msg0 | msg1 | msg2]
__device__ int   g_deg[3 * NN];
__device__ int   g_start[3 * NN];
__device__ int   g_cur[3 * NN];
__device__ int   g_bsum[128];
__device__ int   g_csr[3 * EE];

// ---------------- packed f32x2 helpers -----------------------------------------
__device__ __forceinline__ unsigned long long pk2(float lo, float hi) {
    unsigned long long r;
    asm("mov.b64 %0, {%1, %2};" : "=l"(r) : "f"(lo), "f"(hi));
    return r;
}
__device__ __forceinline__ void upk2(unsigned long long v, float& lo, float& hi) {
    asm("mov.b64 {%0, %1}, %2;" : "=f"(lo), "=f"(hi) : "l"(v));
}
__device__ __forceinline__ void fma2(unsigned long long& d, unsigned long long a, unsigned long long b) {
    asm("fma.rn.f32x2 %0, %1, %2, %3;" : "=l"(d) : "l"(a), "l"(b), "l"(d));
}
__device__ __forceinline__ void cp_async16(void* smem, const void* gmem) {
    unsigned s = (unsigned)__cvta_generic_to_shared(smem);
    asm volatile("cp.async.cg.shared.global [%0], [%1], 16;" :: "r"(s), "l"(gmem));
}
__device__ __forceinline__ void cp_commit() { asm volatile("cp.async.commit_group;"); }
__device__ __forceinline__ void cp_wait0()  { asm volatile("cp.async.wait_group 0;"); }

// ---------------- zero init (deg + cur only) -----------------------------------
__global__ void zero_kernel(int M3) {
    int i = blockIdx.x * blockDim.x + threadIdx.x;
    int stride = gridDim.x * blockDim.x;
    for (int k = i; k < M3; k += stride) { g_deg[k] = 0; g_cur[k] = 0; }
}

// ---------------- weight packing (k-major) -------------------------------------
__global__ void pack_w_kernel(const float* __restrict__ Wm0, const float* __restrict__ Wm1,
                              const float* __restrict__ Wm2,
                              const float* __restrict__ Wn0, const float* __restrict__ Wa0,
                              const float* __restrict__ Wn1, const float* __restrict__ Wa1) {
    int gid = blockIdx.x * blockDim.x + threadIdx.x;
    if (gid >= PCPAD * HH) return;
    int j = gid / HH;     // output column
    int k = gid % HH;     // input feature
    float v = 0.f;
    if (j < 576) {
        int b = j / HH;
        int jj = j % HH;
        int t = b >> 1;
        int rowoff = (b & 1) * HH;
        const float* Wm = (t == 0) ? Wm0 : (t == 1) ? Wm1 : Wm2;
        v = Wm[(size_t)(rowoff + k) * HH + jj];
    } else if (j < PC) {
        int q = j - 576;          // 0:el0 1:er0 2:el1 3:er1
        const float* Wn = (q < 2) ? Wn0 : Wn1;
        const float* Wa = (q < 2) ? Wa0 : Wa1;
        int off = (q & 1) * AA;
        float s = 0.f;
        #pragma unroll
        for (int a = 0; a < AA; a++) s += Wn[(size_t)k * AA + a] * Wa[off + a];
        v = s;
    }
    g_WpackT[(size_t)k * PCPAD + j] = v;
}

__global__ void pack_c_kernel(const float* __restrict__ Wm0, const float* __restrict__ bm0,
                              const float* __restrict__ ef0,
                              const float* __restrict__ Wm1, const float* __restrict__ bm1,
                              const float* __restrict__ ef1,
                              const float* __restrict__ Wm2, const float* __restrict__ bm2,
                              const float* __restrict__ ef2) {
    int gid = threadIdx.x;
    if (gid >= 3 * HH) return;
    int t = gid / HH, j = gid % HH;
    const float* Wm = (t == 0) ? Wm0 : (t == 1) ? Wm1 : Wm2;
    const float* bm = (t == 0) ? bm0 : (t == 1) ? bm1 : bm2;
    const float* ef = (t == 0) ? ef0 : (t == 1) ? ef1 : ef2;
    float s = bm[j];
    #pragma unroll
    for (int d = 0; d < 16; d++) s += ef[d] * Wm[(size_t)(192 + d) * HH + j];
    g_CB[gid] = s;
}

// ---------------- GEMM 1: P = h @ Wcat (double-buffered, cp.async B) -----------
__global__ void __launch_bounds__(256) gemm_p_kernel(const float* __restrict__ h, int Nn) {
    __shared__ float As[2][16][132];
    __shared__ float Bs[2][16][132];
    const int bm = blockIdx.y * 128;
    const int bn = blockIdx.x * 128;
    const int tid = threadIdx.x;
    const int tr = (tid >> 4) << 2;
    const int tc = (tid & 15) << 2;
    unsigned long long acc[8][4];
    #pragma unroll
    for (int i = 0; i < 8; i++)
        #pragma unroll
        for (int j = 0; j < 4; j++) acc[i][j] = 0ull;

    float4 pa[2];
    // prologue: tile 0
    #pragma unroll
    for (int it = 0; it < 2; it++) {
        int q = tid + it * 256;
        int k = q >> 5;
        int c4 = (q & 31) << 2;
        cp_async16(&Bs[0][k][c4], &g_WpackT[(size_t)k * PCPAD + bn + c4]);
    }
    cp_commit();
    #pragma unroll
    for (int it = 0; it < 2; it++) {
        int q = tid + it * 256;
        int row = q >> 2, kq = (q & 3) << 2;
        int grow = bm + row;
        pa[it] = (grow < Nn) ? *reinterpret_cast<const float4*>(&h[(size_t)grow * HH + kq])
                             : make_float4(0.f, 0.f, 0.f, 0.f);
    }
    #pragma unroll
    for (int it = 0; it < 2; it++) {
        int q = tid + it * 256;
        int row = q >> 2, kq = (q & 3) << 2;
        As[0][kq + 0][row] = pa[it].x; As[0][kq + 1][row] = pa[it].y;
        As[0][kq + 2][row] = pa[it].z; As[0][kq + 3][row] = pa[it].w;
    }
    cp_wait0();
    __syncthreads();

    int b = 0;
    for (int k0 = 0; k0 < HH; k0 += 16) {
        bool more = (k0 + 16 < HH);
        if (more) {
            #pragma unroll
            for (int it = 0; it < 2; it++) {
                int q = tid + it * 256;
                int k = q >> 5;
                int c4 = (q & 31) << 2;
                cp_async16(&Bs[b ^ 1][k][c4], &g_WpackT[(size_t)(k0 + 16 + k) * PCPAD + bn + c4]);
            }
            cp_commit();
            #pragma unroll
            for (int it = 0; it < 2; it++) {
                int q = tid + it * 256;
                int row = q >> 2, kq = (q & 3) << 2;
                int grow = bm + row;
                pa[it] = (grow < Nn) ? *reinterpret_cast<const float4*>(&h[(size_t)grow * HH + k0 + 16 + kq])
                                     : make_float4(0.f, 0.f, 0.f, 0.f);
            }
        }
        #pragma unroll
        for (int kk = 0; kk < 16; kk++) {
            float4 a0 = *reinterpret_cast<const float4*>(&As[b][kk][tr]);
            float4 a1 = *reinterpret_cast<const float4*>(&As[b][kk][tr + 64]);
            float4 b0 = *reinterpret_cast<const float4*>(&Bs[b][kk][tc]);
            float4 b1 = *reinterpret_cast<const float4*>(&Bs[b][kk][tc + 64]);
            unsigned long long bb[4] = {pk2(b0.x, b0.y), pk2(b0.z, b0.w),
                                        pk2(b1.x, b1.y), pk2(b1.z, b1.w)};
            float aa[8] = {a0.x, a0.y, a0.z, a0.w, a1.x, a1.y, a1.z, a1.w};
            #pragma unroll
            for (int i = 0; i < 8; i++) {
                unsigned long long ar = pk2(aa[i], aa[i]);
                #pragma unroll
                for (int j = 0; j < 4; j++) fma2(acc[i][j], ar, bb[j]);
            }
        }
        if (more) {
            #pragma unroll
            for (int it = 0; it < 2; it++) {
                int q = tid + it * 256;
                int row = q >> 2, kq = (q & 3) << 2;
                As[b ^ 1][kq + 0][row] = pa[it].x; As[b ^ 1][kq + 1][row] = pa[it].y;
                As[b ^ 1][kq + 2][row] = pa[it].z; As[b ^ 1][kq + 3][row] = pa[it].w;
            }
            cp_wait0();
        }
        __syncthreads();
        b ^= 1;
    }

    #pragma unroll
    for (int i = 0; i < 8; i++) {
        int row = bm + ((i < 4) ? (tr + i) : (tr + 64 + i - 4));
        if (row >= Nn) continue;
        #pragma unroll
        for (int half = 0; half < 2; half++) {
            int colbase = bn + tc + half * 64;
            if (colbase < PC) {
                float4 v;
                upk2(acc[i][half * 2 + 0], v.x, v.y);
                upk2(acc[i][half * 2 + 1], v.z, v.w);
                *reinterpret_cast<float4*>(&g_P[(size_t)row * PC + colbase]) = v;
            }
        }
    }
}

// ---------------- CSR build ----------------------------------------------------
__global__ void deg_kernel(const int* __restrict__ dst, int E, int tbase) {
    int e = blockIdx.x * blockDim.x + threadIdx.x;
    if (e >= E) return;
    atomicAdd(&g_deg[tbase + dst[e]], 1);
}

// block scan: each block scans 4096 elements (256 thr x 16)
__global__ void scan_blocks_kernel(int M) {
    __shared__ int s[256];
    int base = blockIdx.x * 4096;
    int tid = threadIdx.x;
    int vals[16];
    int sum = 0;
    #pragma unroll
    for (int i = 0; i < 16; i++) {
        int idx = base + tid * 16 + i;
        int v = (idx < M) ? g_deg[idx] : 0;
        vals[i] = sum;
        sum += v;
    }
    s[tid] = sum;
    __syncthreads();
    #pragma unroll
    for (int off = 1; off < 256; off <<= 1) {
        int t = (tid >= off) ? s[tid - off] : 0;
        __syncthreads();
        if (tid >= off) s[tid] += t;
        __syncthreads();
    }
    int excl = (tid > 0) ? s[tid - 1] : 0;
    #pragma unroll
    for (int i = 0; i < 16; i++) {
        int idx = base + tid * 16 + i;
        if (idx < M) g_start[idx] = excl + vals[i];
    }
    if (tid == 0) g_bsum[blockIdx.x] = s[255];
}

__global__ void scan_tops_kernel(int B) {
    __shared__ int s[128];
    int tid = threadIdx.x;
    s[tid] = (tid < B) ? g_bsum[tid] : 0;
    __syncthreads();
    #pragma unroll
    for (int off = 1; off < 128; off <<= 1) {
        int t = (tid >= off) ? s[tid - off] : 0;
        __syncthreads();
        if (tid >= off) s[tid] += t;
        __syncthreads();
    }
    if (tid < B) g_bsum[tid] = (tid > 0) ? s[tid - 1] : 0;
}

__global__ void scan_add_kernel(int M) {
    int i = blockIdx.x * blockDim.x + threadIdx.x;
    if (i >= M) return;
    g_start[i] += g_bsum[i >> 12];
}

__global__ void fill_kernel(const int* __restrict__ dst, int E, int tbase) {
    int e = blockIdx.x * blockDim.x + threadIdx.x;
    if (e >= E) return;
    int d = tbase + dst[e];
    int pos = atomicAdd(&g_cur[d], 1);
    g_csr[g_start[d] + pos] = e;
}

// ---------------- edge weights (which selects device-global buffer in-kernel) --
__global__ void edge_w_kernel(const int* __restrict__ src, const int* __restrict__ dst,
                              int elo, int ero, int which, int E) {
    int e = blockIdx.x * blockDim.x + threadIdx.x;
    if (e >= E) return;
    int s = src[e], d = dst[e];
    float sc = __ldg(&g_P[(size_t)s * PC + elo]) + __ldg(&g_P[(size_t)d * PC + ero]);
    sc = (sc > 0.f) ? sc : 0.01f * sc;
    float* wbuf = (which == 0) ? g_w0 : g_w1;   // resolved in device code
    wbuf[e] = expf(sc);
}

// ---------------- dst-parallel aggregation (24 threads / node / type) ----------
__global__ void agg_kernel(const int* __restrict__ src0, const int* __restrict__ src1,
                           const int* __restrict__ src2, int Nn) {
    int gid = blockIdx.x * blockDim.x + threadIdx.x;
    int g = gid / 24;
    int c = gid % 24;
    if (g >= 3 * Nn) return;
    int t = g / Nn;
    int n = g - t * Nn;
    int start = g_start[g];
    int cnt = g_deg[g];
    const int* src = (t == 0) ? src0 : (t == 1) ? src1 : src2;
    const float* wb = (t == 0) ? g_w0 : g_w1;   // unused for t==2
    int aoff = t * 192;
    int c4 = c << 2;

    float4 acc = make_float4(0.f, 0.f, 0.f, 0.f);
    float den = 0.f;
    int eid_n = 0, s_n = 0;
    if (cnt > 0) { eid_n = g_csr[start]; s_n = src[eid_n]; }
    for (int i = 0; i < cnt; i++) {
        int eid = eid_n, s = s_n;
        if (i + 1 < cnt) { eid_n = g_csr[start + i + 1]; s_n = src[eid_n]; }
        float w = (t < 2) ? __ldg(&wb[eid]) : 1.f;
        float4 a = *reinterpret_cast<const float4*>(&g_P[(size_t)s * PC + aoff + c4]);
        acc.x += w * a.x; acc.y += w * a.y; acc.z += w * a.z; acc.w += w * a.w;
        den += w;
    }

    float4 outv = make_float4(0.f, 0.f, 0.f, 0.f);
    if (cnt > 0) {
        float r = 1.f / den;
        float4 bv = *reinterpret_cast<const float4*>(&g_P[(size_t)n * PC + aoff + 96 + c4]);
        float4 cb = *reinterpret_cast<const float4*>(&g_CB[t * HH + c4]);
        outv = make_float4(acc.x * r + bv.x + cb.x, acc.y * r + bv.y + cb.y,
                           acc.z * r + bv.z + cb.z, acc.w * r + bv.w + cb.w);
    }
    *reinterpret_cast<float4*>(&g_X[(size_t)n * 384 + 96 + t * 96 + c4]) = outv;
}

__global__ void copy_h_kernel(const float* __restrict__ h, int Nn) {
    int gid = blockIdx.x * blockDim.x + threadIdx.x;
    int n = gid / 24, c = gid % 24;
    if (n >= Nn) return;
    int c4 = c << 2;
    *reinterpret_cast<float4*>(&g_X[(size_t)n * 384 + c4]) =
        *reinterpret_cast<const float4*>(&h[(size_t)n * HH + c4]);
}

// ---------------- GEMM 2: out = relu(X @ Wu + bu) (double-buffered) ------------
__global__ void __launch_bounds__(256) gemm_out_kernel(const float* __restrict__ Wu,
                                                       const float* __restrict__ bu,
                                                       float* __restrict__ out, int Nn) {
    __shared__ float As[2][16][132];
    __shared__ float Bs[2][16][100];
    const int bm = blockIdx.x * 128;
    const int tid = threadIdx.x;
    const int tr = (tid >> 4) << 2;
    const int tc = (tid & 15) * 6;
    unsigned long long acc[8][3];
    #pragma unroll
    for (int i = 0; i < 8; i++)
        #pragma unroll
        for (int j = 0; j < 3; j++) acc[i][j] = 0ull;

    float4 pa[2];
    // prologue: tile 0
    #pragma unroll
    for (int it = 0; it < 2; it++) {
        int q = tid + it * 256;
        if (q < 384) {
            int k = q / 24;
            int c4 = (q % 24) << 2;
            cp_async16(&Bs[0][k][c4], &Wu[(size_t)k * HH + c4]);
        }
    }
    cp_commit();
    #pragma unroll
    for (int it = 0; it < 2; it++) {
        int q = tid + it * 256;
        int row = q >> 2, kq = (q & 3) << 2;
        int grow = bm + row;
        pa[it] = (grow < Nn) ? *reinterpret_cast<const float4*>(&g_X[(size_t)grow * 384 + kq])
                             : make_float4(0.f, 0.f, 0.f, 0.f);
    }
    #pragma unroll
    for (int it = 0; it < 2; it++) {
        int q = tid + it * 256;
        int row = q >> 2, kq = (q & 3) << 2;
        As[0][kq + 0][row] = pa[it].x; As[0][kq + 1][row] = pa[it].y;
        As[0][kq + 2][row] = pa[it].z; As[0][kq + 3][row] = pa[it].w;
    }
    cp_wait0();
    __syncthreads();

    int b = 0;
    for (int k0 = 0; k0 < 384; k0 += 16) {
        bool more = (k0 + 16 < 384);
        if (more) {
            #pragma unroll
            for (int it = 0; it < 2; it++) {
                int q = tid + it * 256;
                if (q < 384) {
                    int k = q / 24;
                    int c4 = (q % 24) << 2;
                    cp_async16(&Bs[b ^ 1][k][c4], &Wu[(size_t)(k0 + 16 + k) * HH + c4]);
                }
            }
            cp_commit();
            #pragma unroll
            for (int it = 0; it < 2; it++) {
                int q = tid + it * 256;
                int row = q >> 2, kq = (q & 3) << 2;
                int grow = bm + row;
                pa[it] = (grow < Nn) ? *reinterpret_cast<const float4*>(&g_X[(size_t)grow * 384 + k0 + 16 + kq])
                                     : make_float4(0.f, 0.f, 0.f, 0.f);
            }
        }
        #pragma unroll
        for (int kk = 0; kk < 16; kk++) {
            float4 a0 = *reinterpret_cast<const float4*>(&As[b][kk][tr]);
            float4 a1 = *reinterpret_cast<const float4*>(&As[b][kk][tr + 64]);
            float2 b0 = *reinterpret_cast<const float2*>(&Bs[b][kk][tc]);
            float2 b1 = *reinterpret_cast<const float2*>(&Bs[b][kk][tc + 2]);
            float2 b2 = *reinterpret_cast<const float2*>(&Bs[b][kk][tc + 4]);
            unsigned long long bb[3] = {pk2(b0.x, b0.y), pk2(b1.x, b1.y), pk2(b2.x, b2.y)};
            float aa[8] = {a0.x, a0.y, a0.z, a0.w, a1.x, a1.y, a1.z, a1.w};
            #pragma unroll
            for (int i = 0; i < 8; i++) {
                unsigned long long ar = pk2(aa[i], aa[i]);
                #pragma unroll
                for (int j = 0; j < 3; j++) fma2(acc[i][j], ar, bb[j]);
            }
        }
        if (more) {
            #pragma unroll
            for (int it = 0; it < 2; it++) {
                int q = tid + it * 256;
                int row = q >> 2, kq = (q & 3) << 2;
                As[b ^ 1][kq + 0][row] = pa[it].x; As[b ^ 1][kq + 1][row] = pa[it].y;
                As[b ^ 1][kq + 2][row] = pa[it].z; As[b ^ 1][kq + 3][row] = pa[it].w;
            }
            cp_wait0();
        }
        __syncthreads();
        b ^= 1;
    }

    float bias[6];
    #pragma unroll
    for (int j = 0; j < 6; j++) bias[j] = __ldg(&bu[tc + j]);

    #pragma unroll
    for (int i = 0; i < 8; i++) {
        int row = bm + ((i < 4) ? (tr + i) : (tr + 64 + i - 4));
        if (row >= Nn) continue;
        float v[6];
        upk2(acc[i][0], v[0], v[1]);
        upk2(acc[i][1], v[2], v[3]);
        upk2(acc[i][2], v[4], v[5]);
        #pragma unroll
        for (int j = 0; j < 6; j++)
            out[(size_t)row * HH + tc + j] = fmaxf(v[j] + bias[j], 0.f);
    }
}

// ---------------- launch -------------------------------------------------------
extern "C" void kernel_launch(void* const* d_in, const int* in_sizes, int n_in,
                              void* d_out, int out_size) {
    const float* h    = (const float*)d_in[0];
    const int*   src0 = (const int*)d_in[1];
    const int*   dst0 = (const int*)d_in[2];
    const int*   src1 = (const int*)d_in[3];
    const int*   dst1 = (const int*)d_in[4];
    const int*   src2 = (const int*)d_in[5];
    const int*   dst2 = (const int*)d_in[6];
    const float* Wm0  = (const float*)d_in[7];
    const float* bm0  = (const float*)d_in[8];
    const float* ef0  = (const float*)d_in[9];
    const float* Wm1  = (const float*)d_in[10];
    const float* bm1  = (const float*)d_in[11];
    const float* ef1  = (const float*)d_in[12];
    const float* Wm2  = (const float*)d_in[13];
    const float* bm2  = (const float*)d_in[14];
    const float* ef2  = (const float*)d_in[15];
    const float* Wn0  = (const float*)d_in[16];
    const float* Wa0  = (const float*)d_in[17];
    const float* Wn1  = (const float*)d_in[18];
    const float* Wa1  = (const float*)d_in[19];
    const float* Wu   = (const float*)d_in[20];
    const float* bu   = (const float*)d_in[21];
    float* out = (float*)d_out;

    int Nn = in_sizes[0] / HH;
    int E0 = in_sizes[1];
    int E1 = in_sizes[3];
    int E2 = in_sizes[5];
    int M3 = 3 * Nn;
    int B = (M3 + 4095) / 4096;

    zero_kernel<<<256, 256>>>(M3);
    pack_w_kernel<<<(PCPAD * HH + 255) / 256, 256>>>(Wm0, Wm1, Wm2, Wn0, Wa0, Wn1, Wa1);
    pack_c_kernel<<<1, 3 * HH>>>(Wm0, bm0, ef0, Wm1, bm1, ef1, Wm2, bm2, ef2);

    // CSR build (independent of GEMM)
    deg_kernel<<<(E0 + 255) / 256, 256>>>(dst0, E0, 0);
    deg_kernel<<<(E1 + 255) / 256, 256>>>(dst1, E1, Nn);
    deg_kernel<<<(E2 + 255) / 256, 256>>>(dst2, E2, 2 * Nn);
    scan_blocks_kernel<<<B, 256>>>(M3);
    scan_tops_kernel<<<1, 128>>>(B);
    scan_add_kernel<<<(M3 + 255) / 256, 256>>>(M3);
    fill_kernel<<<(E0 + 255) / 256, 256>>>(dst0, E0, 0);
    fill_kernel<<<(E1 + 255) / 256, 256>>>(dst1, E1, Nn);
    fill_kernel<<<(E2 + 255) / 256, 256>>>(dst2, E2, 2 * Nn);

    dim3 g1(PCPAD / 128, (Nn + 127) / 128);
    gemm_p_kernel<<<g1, 256>>>(h, Nn);

    edge_w_kernel<<<(E0 + 255) / 256, 256>>>(src0, dst0, 576, 577, 0, E0);
    edge_w_kernel<<<(E1 + 255) / 256, 256>>>(src1, dst1, 578, 579, 1, E1);

    agg_kernel<<<(3 * Nn * 24 + 95) / 96, 96>>>(src0, src1, src2, Nn);
    copy_h_kernel<<<(Nn * 24 + 255) / 256, 256>>>(h, Nn);

    gemm_out_kernel<<<(Nn + 127) / 128, 256>>>(Wu, bu, out, Nn);
}